// round 11
// baseline (speedup 1.0000x reference)
#include <cuda_runtime.h>
#include <math.h>
#include <stdint.h>

// Problem constants
#define BB 64
#define CC 16
#define FF 2048
#define JT 25            // stored joints per feature row
#define SPB 4            // series per block
#define NPARTS 6         // 24 joints / 4
#define NT 256           // 8 warps: 2 per series
#define RS 2056          // padded row stride (words): mod 32 == 8
#define SCAP 224         // per-task filtered scratch capacity (cw~162, +5sigma)

#define DATA_WORDS (SPB * RS)                 // 8224
#define SCR_OFF    DATA_WORDS                 // 8224
#define HIST_OFF   (SCR_OFF + 8 * SCAP)       // 10016
#define REC_OFF    (HIST_OFF + 8 * 256)       // 12064
#define QOUT_OFF   (REC_OFF + 8 * 16)         // 12192
#define SMEM_WORDS (QOUT_OFF + SPB * 8)       // 12224
#define SMEM_BYTES (SMEM_WORDS * 4)           // 48896 -> 4 blocks/SM

__device__ float g_stat2[BB * CC * 16 * 12];   // (b, c, s, j)
__device__ float g_weff[5 * 16 * 16 * 12];     // (cls, c, s, j)

__device__ __forceinline__ unsigned f2key(float x) {
    unsigned b = __float_as_uint(x);
    return b ^ ((unsigned)(((int)b) >> 31) | 0x80000000u);
}
__device__ __forceinline__ float key2f(unsigned k) {
    unsigned u = (k & 0x80000000u) ? (k & 0x7fffffffu) : ~k;
    return __uint_as_float(u);
}

// ---------------------------------------------------------------------------
// 256-bin histogram rank search (warp-uniform r). Returns bin; updates r to
// rank-within-bin; outputs bin count.
// ---------------------------------------------------------------------------
__device__ __forceinline__ int warp_find_bin256(const unsigned* hist, int lane,
                                                int& r, int& bincount) {
    const unsigned full = 0xffffffffu;
    unsigned c[8]; unsigned run = 0;
#pragma unroll
    for (int t = 0; t < 8; t++) { c[t] = hist[lane * 8 + t]; run += c[t]; }
    unsigned inc = run;
#pragma unroll
    for (int d = 1; d < 32; d <<= 1) {
        unsigned v = __shfl_up_sync(full, inc, d);
        if (lane >= d) inc += v;
    }
    unsigned acc = inc - run;
    int bin = -1, newr = 0; unsigned bc = 0;
#pragma unroll
    for (int t = 0; t < 8; t++) {
        if (bin < 0 && (int)acc <= r && r < (int)(acc + c[t])) {
            bin = lane * 8 + t; newr = r - (int)acc; bc = c[t];
        }
        acc += c[t];
    }
    unsigned m = __ballot_sync(full, bin >= 0);
    int srcl = __ffs(m) - 1;
    bin  = __shfl_sync(full, bin, srcl);
    newr = __shfl_sync(full, newr, srcl);
    bc   = __shfl_sync(full, bc, srcl);
    r = newr; bincount = (int)bc;
    return bin;
}

// ---------------------------------------------------------------------------
// Correctness fallback: exact rank-r key via 32-pass bisection over the GMEM
// series (stride 25 floats). Rare (>=5 sigma pivot margins); always exact.
// ---------------------------------------------------------------------------
__device__ unsigned gsel_gmem(const float* col0, int lane, int r) {
    const unsigned full = 0xffffffffu;
    unsigned Klo = 0u, Khi = 0xffffffffu;
#pragma unroll 1
    while (Klo < Khi) {
        unsigned mid = Klo + ((Khi - Klo) >> 1);
        int cle = 0;
        for (int i = 0; i < 64; i++)
            cle += (f2key(__ldg(col0 + (size_t)(i * 32 + lane) * JT)) <= mid);
#pragma unroll
        for (int d = 16; d; d >>= 1) cle += __shfl_xor_sync(full, cle, d);
        if (r < cle) Khi = mid; else Klo = mid + 1u;
    }
    return Klo;
}

// ---------------------------------------------------------------------------
// Kernel A: one block per (b,c,part); 4 series, 2 warps per series.
// Candidates are compacted into the CONSUMED PREFIX of each half-row
// (in-place), eliminating the separate candidate buffer -> 4 blocks/SM.
// ---------------------------------------------------------------------------
__global__ __launch_bounds__(NT, 4)
void stats_kernel(const float* __restrict__ features,
                  const float* __restrict__ W2, const float* __restrict__ Wl) {
    extern __shared__ unsigned sm[];
    const unsigned full = 0xffffffffu;

    const int blk  = blockIdx.x;
    const int bc   = blk / NPARTS;
    const int part = blk - bc * NPARTS;       // 0..5 -> joints part*4 .. +3
    const int tid  = threadIdx.x;

    const float* src = features + (size_t)bc * (FF * JT) + part * 4;
    float* smf = reinterpret_cast<float*>(sm);

    // ---- phase 1: load 4 joints, transpose to rows (conflict-free) ----
    {
        int jj = tid & 3;
        int f  = tid >> 2;                    // 0..63
#pragma unroll 8
        for (int k = 0; k < 32; k++, f += 64)
            smf[jj * RS + f] = __ldg(src + f * JT + jj);
    }
    __syncthreads();

    const int w    = tid >> 5;
    const int lane = tid & 31;
    const int s    = w >> 1;                  // series 0..3
    const int h    = w & 1;                   // half 0..1

    // window pivots (data ~N(0,1); GMEM bisection fallback covers the rest)
    const float P0 = -0.80f, P1 = -0.55f, P2 = -0.125f,
                P3 =  0.125f, P4 =  0.55f, P5 =  0.80f;

    // ---- phase 2: fused half-scan; candidates compact into consumed prefix ----
    unsigned* rowh = sm + s * RS + h * 1024;
    float s1 = 0.f, s2 = 0.f, s3 = 0.f, s4 = 0.f;
    float mn = INFINITY, mx = -INFINITY;
    int c0 = 0, c1 = 0, c2 = 0;
    int p = 0;                                 // combined window fill
#pragma unroll 4
    for (int i = 0; i < 32; i++) {
        float x = __uint_as_float(rowh[i * 32 + lane]);
        s1 += x;
        float x2 = x * x;
        s2 += x2; s3 += x2 * x; s4 += x2 * x2;
        mn = fminf(mn, x); mx = fmaxf(mx, x);
        bool b0 = x < P0, b1 = x < P1, b2 = x < P2,
             b3 = x < P3, b4 = x < P4, b5 = x < P5;
        c0 += b0; c1 += b2; c2 += b4;
        bool in = (b1 && !b0) || (b3 && !b2) || (b5 && !b4);
        unsigned m = __ballot_sync(full, in);
        // write pos <= 32*i+31 < 32*(i+1): never passes the read frontier;
        // ballot guarantees all lanes loaded x before any store.
        if (in) rowh[p + __popc(m & ((1u << lane) - 1u))] = __float_as_uint(x);
        p += __popc(m);
    }
#pragma unroll
    for (int d = 16; d; d >>= 1) {
        s1 += __shfl_xor_sync(full, s1, d);
        s2 += __shfl_xor_sync(full, s2, d);
        s3 += __shfl_xor_sync(full, s3, d);
        s4 += __shfl_xor_sync(full, s4, d);
        mn = fminf(mn, __shfl_xor_sync(full, mn, d));
        mx = fmaxf(mx, __shfl_xor_sync(full, mx, d));
        c0 += __shfl_xor_sync(full, c0, d);
        c1 += __shfl_xor_sync(full, c1, d);
        c2 += __shfl_xor_sync(full, c2, d);
    }
    unsigned* rec = sm + REC_OFF + w * 16;
    if (lane == 0) {
        rec[0] = __float_as_uint(s1); rec[1] = __float_as_uint(s2);
        rec[2] = __float_as_uint(s3); rec[3] = __float_as_uint(s4);
        rec[4] = __float_as_uint(mn); rec[5] = __float_as_uint(mx);
        rec[6] = (unsigned)c0; rec[7] = (unsigned)c1; rec[8] = (unsigned)c2;
        rec[9] = (unsigned)p;
    }
    __syncthreads();

    // ---- phase 3: 12 selection tasks over 8 warps ----
    const float PL[3] = {-0.80f, -0.125f, 0.55f};
    const float PH[3] = {-0.55f,  0.125f, 0.80f};
    const int   R0[3] = {511, 1023, 1535};

    unsigned* scr  = sm + SCR_OFF + w * SCAP;
    unsigned* hist = sm + HIST_OFF + w * 256;
    float* qout = reinterpret_cast<float*>(sm + QOUT_OFF);

#pragma unroll 1
    for (int pass = 0; pass < 2; pass++) {
        int t = (pass == 0) ? w : (w < 4 ? 8 + w : -1);
        if (t < 0) break;
        int ts = t / 3, v = t - ts * 3;
        const unsigned* r0 = sm + REC_OFF + (2 * ts) * 16;
        const unsigned* r1 = r0 + 16;
        int clow = (int)r0[6 + v] + (int)r1[6 + v];
        int pa = (int)r0[9], pb = (int)r1[9];
        int lr = R0[v] - clow;
        int need1 = (v != 1);
        float Plo = PL[v], Phi = PH[v];
        const unsigned* cb0 = sm + ts * RS;          // candidates in row prefix
        const unsigned* cb1 = cb0 + 1024;

        // pass A: filter window candidates of both halves into scr (keys),
        // tracking count + key min/max.
        int cnt = 0;
        unsigned kmn = 0xffffffffu, kmx = 0u;
#pragma unroll 1
        for (int seg = 0; seg < 2; seg++) {
            const unsigned* cb = seg ? cb1 : cb0;
            int pc = seg ? pb : pa;
            for (int base = 0; base < pc; base += 32) {
                int idx = base + lane;
                float x = (idx < pc) ? __uint_as_float(cb[idx]) : 0.f;
                bool in = (idx < pc) && (x >= Plo) && (x < Phi);
                unsigned m = __ballot_sync(full, in);
                if (in) {
                    int pos = cnt + __popc(m & ((1u << lane) - 1u));
                    if (pos < SCAP) {
                        unsigned k = f2key(x);
                        scr[pos] = k;
                        kmn = min(kmn, k); kmx = max(kmx, k);
                    }
                }
                cnt += __popc(m);
            }
        }
#pragma unroll
        for (int d = 16; d; d >>= 1) {
            kmn = min(kmn, __shfl_xor_sync(full, kmn, d));
            kmx = max(kmx, __shfl_xor_sync(full, kmx, d));
        }
        __syncwarp();

        bool ok = (cnt <= SCAP) && (lr >= 0) && ((lr + need1) < cnt);
        float v0, v1 = 0.f;
        if (ok) {
            unsigned k0, k1;
            if (kmn == kmx) {
                k0 = kmn; k1 = kmn;
            } else {
                // adaptive 8-bit radix rounds over scr (no compaction)
                unsigned prefix = 0u, pmask = 0u;
                unsigned diff = kmn ^ kmx;
                int hib = 31 - __clz(diff);
                int sh = hib > 7 ? hib - 7 : 0;
                int cc = cnt, lrr = lr;
#pragma unroll 1
                for (int round = 0; round < 5; round++) {
#pragma unroll
                    for (int u = 0; u < 8; u++) hist[lane + u * 32] = 0u;
                    __syncwarp();
                    for (int idx = lane; idx < cnt; idx += 32) {
                        unsigned kk = scr[idx];
                        if ((kk & pmask) == prefix)
                            atomicAdd(&hist[(kk >> sh) & 0xFFu], 1u);
                    }
                    __syncwarp();
                    int bcnt;
                    int b = warp_find_bin256(hist, lane, lrr, bcnt);
                    prefix |= (unsigned)b << sh;
                    pmask  |= 0xFFu << sh;
                    cc = bcnt;
                    __syncwarp();
                    if (cc <= 32 || sh == 0) break;
                    sh = (sh >= 8) ? sh - 8 : 0;
                }
                // final gather of matching keys (<=32, or all-identical)
                unsigned* s32 = hist;   // hist dead now
                unsigned mna = 0xffffffffu;
                int pos = 0;
                for (int base = 0; base < cnt; base += 32) {
                    int idx = base + lane;
                    bool match = false; unsigned kk = 0u;
                    if (idx < cnt) {
                        kk = scr[idx];
                        unsigned masked = kk & pmask;
                        if (masked == prefix) match = true;
                        else if (masked > prefix) mna = min(mna, kk);
                    }
                    unsigned m = __ballot_sync(full, match);
                    if (match) {
                        int p2 = pos + __popc(m & ((1u << lane) - 1u));
                        if (p2 < 32) s32[p2] = kk;
                    }
                    pos += __popc(m);
                }
#pragma unroll
                for (int d = 16; d; d >>= 1)
                    mna = min(mna, __shfl_xor_sync(full, mna, d));
                __syncwarp();
                if (cc <= 32) {
                    unsigned vv = (lane < cc) ? s32[lane] : 0xffffffffu;
#pragma unroll
                    for (int k2 = 2; k2 <= 32; k2 <<= 1)
#pragma unroll
                        for (int j = k2 >> 1; j; j >>= 1) {
                            unsigned o = __shfl_xor_sync(full, vv, j);
                            bool keepMin = ((lane & j) == 0) == ((lane & k2) == 0);
                            vv = keepMin ? min(vv, o) : max(vv, o);
                        }
                    k0 = __shfl_sync(full, vv, lrr);
                    unsigned k1n = __shfl_sync(full, vv, (lrr + 1) & 31);
                    k1 = (lrr + 1 < cc) ? k1n : mna;
                } else {
                    // sh reached 0 with cc>32: all matching keys identical
                    k0 = s32[0];
                    k1 = (lrr + 1 < cc) ? k0 : mna;
                }
            }
            v0 = key2f(k0);
            if (need1) v1 = key2f(k1);
        } else {
            const float* col0 = features + (size_t)bc * (FF * JT)
                                + part * 4 + ts;
            v0 = key2f(gsel_gmem(col0, lane, R0[v]));
            if (need1) v1 = key2f(gsel_gmem(col0, lane, R0[v] + 1));
        }
        if (lane == 0) {
            float* qo = qout + ts * 8;
            if (v == 0) { qo[0] = v0; qo[1] = v1; }
            else if (v == 1) { qo[2] = v0; }
            else { qo[3] = v0; qo[4] = v1; }
        }
    }
    __syncthreads();

    // ---- phase 4: finalize (warp 0, lanes 0..3 -> one series each) ----
    if (w == 0 && lane < SPB) {
        int ts = lane;
        const unsigned* r0 = sm + REC_OFF + (2 * ts) * 16;
        const unsigned* r1 = r0 + 16;
        float ts1 = __uint_as_float(r0[0]) + __uint_as_float(r1[0]);
        float ts2 = __uint_as_float(r0[1]) + __uint_as_float(r1[1]);
        float ts3 = __uint_as_float(r0[2]) + __uint_as_float(r1[2]);
        float ts4 = __uint_as_float(r0[3]) + __uint_as_float(r1[3]);
        float tmn = fminf(__uint_as_float(r0[4]), __uint_as_float(r1[4]));
        float tmx = fmaxf(__uint_as_float(r0[5]), __uint_as_float(r1[5]));
        const float* qo = qout + ts * 8;

        const float n = 2048.f;
        float mean = ts1 / n;
        float m2 = ts2 / n, m3 = ts3 / n, m4 = ts4 / n;
        float varp = m2 - mean * mean;
        float var1 = varp * (n / (n - 1.f));
        float sd = sqrtf(var1);
        float mu2 = mean * mean;
        float m4c = m4 - 4.f * mean * m3 + 6.f * mu2 * m2 - 3.f * mu2 * mu2;
        float kurt = m4c / (var1 * var1) - 3.f;
        float q25 = 0.25f * qo[0] + 0.75f * qo[1];   // pos 511.75
        float med = qo[2];                            // pos 1023
        float q75 = 0.75f * qo[3] + 0.25f * qo[4];   // pos 1535.25

        int jg = part * SPB + ts;                     // 0..23
        int base = (jg < 12) ? 0 : 8;
        int col  = (jg < 12) ? jg : (jg - 12);
        float* o = g_stat2 + ((size_t)bc * 16 + base) * 12 + col;
        o[0 * 12] = tmx;
        o[1 * 12] = q25;
        o[2 * 12] = med;
        o[3 * 12] = q75;
        o[4 * 12] = mean;
        o[5 * 12] = sd;
        o[6 * 12] = tmx - tmn;
        o[7 * 12] = kurt;
    }

    // ---- weff tail folded in: blocks 0..119, threads 0..127 ----
    if (blk < 120 && tid < 128) {
        int idx = blk * 128 + tid;                    // 0 .. 15359
        int j   = idx % 12;
        int sx  = (idx / 12) & 15;
        int cx  = (idx / 192) & 15;
        int cls = idx / 3072;
        float a = 0.f;
#pragma unroll 8
        for (int e = 0; e < 64; e++)
            a += __ldg(&Wl[cls * 1024 + e * 16 + sx]) *
                 __ldg(&W2[(e * 16 + cx) * 12 + j]);
        g_weff[idx] = a;
    }
}

// ---------------------------------------------------------------------------
// Kernel B: logits[b,cls] = dot(stat2[b], weff[cls]) + sum b2*Wl + bl
// ---------------------------------------------------------------------------
__global__ __launch_bounds__(128)
void logits_kernel(const float* __restrict__ Wl, const float* __restrict__ b2,
                   const float* __restrict__ bl, float* __restrict__ out) {
    __shared__ float part[4];
    const unsigned full = 0xffffffffu;
    int blk = blockIdx.x;
    int b = blk / 5, cls = blk - b * 5;
    int tid = threadIdx.x;
    const float* st = g_stat2 + (size_t)b * 3072;
    const float* wf = g_weff + (size_t)cls * 3072;
    float a = 0.f;
    for (int i = tid; i < 3072; i += 128) a += st[i] * wf[i];
    for (int k = tid; k < 1024; k += 128)
        a += __ldg(&b2[k >> 4]) * __ldg(&Wl[cls * 1024 + k]);
#pragma unroll
    for (int d = 16; d; d >>= 1) a += __shfl_xor_sync(full, a, d);
    if ((tid & 31) == 0) part[tid >> 5] = a;
    __syncthreads();
    if (tid == 0)
        out[b * 5 + cls] = part[0] + part[1] + part[2] + part[3] + bl[cls];
}

// ---------------------------------------------------------------------------
extern "C" void kernel_launch(void* const* d_in, const int* in_sizes, int n_in,
                              void* d_out, int out_size) {
    const float* features = (const float*)d_in[0];
    // d_in[1]=W1, d_in[2]=b1 : dead in the reference (result discarded)
    const float* W2 = (const float*)d_in[3];
    const float* b2 = (const float*)d_in[4];
    const float* Wl = (const float*)d_in[5];
    const float* bl = (const float*)d_in[6];
    float* out = (float*)d_out;

    cudaFuncSetAttribute(stats_kernel,
                         cudaFuncAttributeMaxDynamicSharedMemorySize,
                         SMEM_BYTES);

    stats_kernel<<<BB * CC * NPARTS, NT, SMEM_BYTES>>>(features, W2, Wl);
    logits_kernel<<<BB * 5, 128>>>(Wl, b2, bl, out);
}

// round 12
// speedup vs baseline: 1.1566x; 1.1566x over previous
#include <cuda_runtime.h>
#include <math.h>
#include <stdint.h>

// Problem constants
#define BB 64
#define CC 16
#define FF 2048
#define JT 25            // stored joints per feature row
#define SPB 4            // series per block
#define NPARTS 6         // 24 joints / 4
#define NT 256           // 8 warps: 2 per series
#define RS 2056          // padded row stride (words): mod 32 == 8, 16B-aligned
#define CAPH 320         // combined-candidate capacity per half-series
#define SCAP 288         // per-task filtered scratch capacity

#define DATA_WORDS (SPB * RS)                 // 8224
#define CAND_OFF   DATA_WORDS                 // 8224
#define SCR_OFF    (CAND_OFF + 8 * CAPH)      // 10784
#define HIST_OFF   (SCR_OFF + 8 * SCAP)       // 13088
#define REC_OFF    (HIST_OFF + 8 * 256)       // 15136  (32 records x 12 words)
#define PCNT_OFF   (REC_OFF + 32 * 12)        // 15520
#define QOUT_OFF   (PCNT_OFF + 8)             // 15528
#define SMEM_WORDS (QOUT_OFF + SPB * 8)       // 15560
#define SMEM_BYTES (SMEM_WORDS * 4)           // 62240 -> 3 blocks/SM

__device__ float g_stat2[BB * CC * 16 * 12];   // (b, c, s, j)
__device__ float g_weff[5 * 16 * 16 * 12];     // (cls, c, s, j)

__device__ __forceinline__ unsigned f2key(float x) {
    unsigned b = __float_as_uint(x);
    return b ^ ((unsigned)(((int)b) >> 31) | 0x80000000u);
}
__device__ __forceinline__ float key2f(unsigned k) {
    unsigned u = (k & 0x80000000u) ? (k & 0x7fffffffu) : ~k;
    return __uint_as_float(u);
}

// ---------------------------------------------------------------------------
// 256-bin histogram rank search (warp-uniform r). Returns bin; updates r to
// rank-within-bin; outputs bin count.
// ---------------------------------------------------------------------------
__device__ __forceinline__ int warp_find_bin256(const unsigned* hist, int lane,
                                                int& r, int& bincount) {
    const unsigned full = 0xffffffffu;
    unsigned c[8]; unsigned run = 0;
#pragma unroll
    for (int t = 0; t < 8; t++) { c[t] = hist[lane * 8 + t]; run += c[t]; }
    unsigned inc = run;
#pragma unroll
    for (int d = 1; d < 32; d <<= 1) {
        unsigned v = __shfl_up_sync(full, inc, d);
        if (lane >= d) inc += v;
    }
    unsigned acc = inc - run;
    int bin = -1, newr = 0; unsigned bc = 0;
#pragma unroll
    for (int t = 0; t < 8; t++) {
        if (bin < 0 && (int)acc <= r && r < (int)(acc + c[t])) {
            bin = lane * 8 + t; newr = r - (int)acc; bc = c[t];
        }
        acc += c[t];
    }
    unsigned m = __ballot_sync(full, bin >= 0);
    int srcl = __ffs(m) - 1;
    bin  = __shfl_sync(full, bin, srcl);
    newr = __shfl_sync(full, newr, srcl);
    bc   = __shfl_sync(full, bc, srcl);
    r = newr; bincount = (int)bc;
    return bin;
}

// ---------------------------------------------------------------------------
// Correctness fallback: exact rank-r key via bisection over the intact row.
// ---------------------------------------------------------------------------
__device__ unsigned generic_select_row(const unsigned* row, int lane, int r) {
    const unsigned full = 0xffffffffu;
    unsigned Klo = 0u, Khi = 0xffffffffu;
#pragma unroll 1
    while (Klo < Khi) {
        unsigned mid = Klo + ((Khi - Klo) >> 1);
        int cle = 0;
        for (int i = 0; i < 64; i++)
            cle += (f2key(__uint_as_float(row[i * 32 + lane])) <= mid);
#pragma unroll
        for (int d = 16; d; d >>= 1) cle += __shfl_xor_sync(full, cle, d);
        if (r < cle) Khi = mid; else Klo = mid + 1u;
    }
    return Klo;
}

// ---------------------------------------------------------------------------
// Kernel A: one block per (b,c,part); 4 series, 2 warps per series.
// Moments/counts fused into the GMEM load (fills LDG stall slots); phase 2
// is gather-only with float4 smem reads; selection identical to R8.
// ---------------------------------------------------------------------------
__global__ __launch_bounds__(NT)
void stats_kernel(const float* __restrict__ features,
                  const float* __restrict__ W2, const float* __restrict__ Wl) {
    extern __shared__ unsigned sm[];
    const unsigned full = 0xffffffffu;

    const int blk  = blockIdx.x;
    const int bc   = blk / NPARTS;
    const int part = blk - bc * NPARTS;       // 0..5 -> joints part*4 .. +3
    const int tid  = threadIdx.x;
    const int w    = tid >> 5;
    const int lane = tid & 31;

    const float* src = features + (size_t)bc * (FF * JT) + part * 4;
    float* smf = reinterpret_cast<float*>(sm);

    // window pivots (data ~N(0,1); smem bisection fallback covers the rest)
    const float P0 = -0.80f, P1 = -0.55f, P2 = -0.125f,
                P3 =  0.125f, P4 =  0.55f, P5 =  0.80f;

    // ---- phase 1: load + transpose + moments + counts (in LDG shadow) ----
    {
        int jj = tid & 3;
        int f  = tid >> 2;                    // 0..63, stride 64
        float s1 = 0.f, s2 = 0.f, s3 = 0.f, s4 = 0.f;
        float mn = INFINITY, mx = -INFINITY;
        int c0 = 0, c1 = 0, c2 = 0;
#pragma unroll 8
        for (int k = 0; k < 32; k++, f += 64) {
            float x = __ldg(src + (size_t)f * JT + jj);
            smf[jj * RS + f] = x;
            s1 += x;
            float x2 = x * x;
            s2 += x2; s3 += x2 * x; s4 += x2 * x2;
            mn = fminf(mn, x); mx = fmaxf(mx, x);
            c0 += (x < P0); c1 += (x < P2); c2 += (x < P4);
        }
        // reduce over the 8 lanes sharing jj (xor 4,8,16 preserves lane&3)
#pragma unroll
        for (int d = 4; d <= 16; d <<= 1) {
            s1 += __shfl_xor_sync(full, s1, d);
            s2 += __shfl_xor_sync(full, s2, d);
            s3 += __shfl_xor_sync(full, s3, d);
            s4 += __shfl_xor_sync(full, s4, d);
            mn = fminf(mn, __shfl_xor_sync(full, mn, d));
            mx = fmaxf(mx, __shfl_xor_sync(full, mx, d));
            c0 += __shfl_xor_sync(full, c0, d);
            c1 += __shfl_xor_sync(full, c1, d);
            c2 += __shfl_xor_sync(full, c2, d);
        }
        if (lane < 4) {     // lane == jj for these lanes
            unsigned* r = sm + REC_OFF + (w * 4 + lane) * 12;
            r[0] = __float_as_uint(s1); r[1] = __float_as_uint(s2);
            r[2] = __float_as_uint(s3); r[3] = __float_as_uint(s4);
            r[4] = __float_as_uint(mn); r[5] = __float_as_uint(mx);
            r[6] = (unsigned)c0; r[7] = (unsigned)c1; r[8] = (unsigned)c2;
        }
    }
    __syncthreads();

    const int s = w >> 1;                     // series 0..3
    const int h = w & 1;                      // half 0..1

    // ---- phase 2: gather-only half-scan (float4 reads, combined windows) ----
    {
        const float4* rowh4 = reinterpret_cast<const float4*>(
            reinterpret_cast<const float*>(sm) + s * RS + h * 1024);
        unsigned* cand = sm + CAND_OFF + w * CAPH;
        int p = 0;
#pragma unroll 2
        for (int i = 0; i < 8; i++) {
            float4 xv = rowh4[i * 32 + lane];
#pragma unroll
            for (int e = 0; e < 4; e++) {
                float x = (e == 0) ? xv.x : (e == 1) ? xv.y
                        : (e == 2) ? xv.z : xv.w;
                bool b0 = x < P0, b1 = x < P1, b2 = x < P2,
                     b3 = x < P3, b4 = x < P4, b5 = x < P5;
                bool in = (b1 && !b0) || (b3 && !b2) || (b5 && !b4);
                unsigned m = __ballot_sync(full, in);
                if (in) {
                    int pos = p + __popc(m & ((1u << lane) - 1u));
                    if (pos < CAPH) cand[pos] = __float_as_uint(x);
                }
                p += __popc(m);
            }
        }
        if (lane == 0) sm[PCNT_OFF + w] = (unsigned)p;
    }
    __syncthreads();

    // ---- phase 3: 12 selection tasks over 8 warps (R8-identical core) ----
    const float PL[3] = {-0.80f, -0.125f, 0.55f};
    const float PH[3] = {-0.55f,  0.125f, 0.80f};
    const int   R0[3] = {511, 1023, 1535};

    unsigned* scr  = sm + SCR_OFF + w * SCAP;
    unsigned* hist = sm + HIST_OFF + w * 256;
    float* qout = reinterpret_cast<float*>(sm + QOUT_OFF);

#pragma unroll 1
    for (int pass = 0; pass < 2; pass++) {
        int t = (pass == 0) ? w : (w < 4 ? 8 + w : -1);
        if (t < 0) break;
        int ts = t / 3, v = t - ts * 3;

        // count below window: sum records over the 8 warps for series ts
        int cb = (lane < 8) ? (int)sm[REC_OFF + (lane * 4 + ts) * 12 + 6 + v] : 0;
#pragma unroll
        for (int d = 1; d <= 4; d <<= 1) cb += __shfl_xor_sync(full, cb, d);
        cb = __shfl_sync(full, cb, 0);

        int pa = (int)sm[PCNT_OFF + 2 * ts];
        int pb = (int)sm[PCNT_OFF + 2 * ts + 1];
        int lr = R0[v] - cb;
        int need1 = (v != 1);
        float Plo = PL[v], Phi = PH[v];
        const unsigned* cb0 = sm + CAND_OFF + (2 * ts) * CAPH;
        const unsigned* cb1 = cb0 + CAPH;
        bool overflow = (pa > CAPH) || (pb > CAPH);

        // pass A: filter window candidates into scr (keys) + count + min/max
        int cnt = 0;
        unsigned kmn = 0xffffffffu, kmx = 0u;
        if (!overflow) {
#pragma unroll 1
            for (int seg = 0; seg < 2; seg++) {
                const unsigned* cb2 = seg ? cb1 : cb0;
                int pc = seg ? pb : pa;
                for (int base = 0; base < pc; base += 32) {
                    int idx = base + lane;
                    float x = (idx < pc) ? __uint_as_float(cb2[idx]) : 0.f;
                    bool in = (idx < pc) && (x >= Plo) && (x < Phi);
                    unsigned m = __ballot_sync(full, in);
                    if (in) {
                        int pos = cnt + __popc(m & ((1u << lane) - 1u));
                        if (pos < SCAP) {
                            unsigned k = f2key(x);
                            scr[pos] = k;
                            kmn = min(kmn, k); kmx = max(kmx, k);
                        }
                    }
                    cnt += __popc(m);
                }
            }
#pragma unroll
            for (int d = 16; d; d >>= 1) {
                kmn = min(kmn, __shfl_xor_sync(full, kmn, d));
                kmx = max(kmx, __shfl_xor_sync(full, kmx, d));
            }
            __syncwarp();
        }

        bool ok = !overflow && (cnt <= SCAP) && (lr >= 0) &&
                  ((lr + need1) < cnt);
        float v0, v1 = 0.f;
        if (ok) {
            unsigned k0, k1;
            if (kmn == kmx) {
                k0 = kmn; k1 = kmn;
            } else {
                // adaptive 8-bit radix rounds over scr (no compaction)
                unsigned prefix = 0u, pmask = 0u;
                unsigned diff = kmn ^ kmx;
                int hib = 31 - __clz(diff);
                int sh = hib > 7 ? hib - 7 : 0;
                int cc = cnt, lrr = lr;
#pragma unroll 1
                for (int round = 0; round < 5; round++) {
#pragma unroll
                    for (int u = 0; u < 8; u++) hist[lane + u * 32] = 0u;
                    __syncwarp();
                    for (int idx = lane; idx < cnt; idx += 32) {
                        unsigned kk = scr[idx];
                        if ((kk & pmask) == prefix)
                            atomicAdd(&hist[(kk >> sh) & 0xFFu], 1u);
                    }
                    __syncwarp();
                    int bcnt;
                    int b = warp_find_bin256(hist, lane, lrr, bcnt);
                    prefix |= (unsigned)b << sh;
                    pmask  |= 0xFFu << sh;
                    cc = bcnt;
                    __syncwarp();
                    if (cc <= 32 || sh == 0) break;
                    sh = (sh >= 8) ? sh - 8 : 0;
                }
                // final gather of matching keys (<=32, or all-identical)
                unsigned* s32 = hist;   // hist dead now
                unsigned mna = 0xffffffffu;
                int pos = 0;
                for (int base = 0; base < cnt; base += 32) {
                    int idx = base + lane;
                    bool match = false; unsigned kk = 0u;
                    if (idx < cnt) {
                        kk = scr[idx];
                        unsigned masked = kk & pmask;
                        if (masked == prefix) match = true;
                        else if (masked > prefix) mna = min(mna, kk);
                    }
                    unsigned m = __ballot_sync(full, match);
                    if (match) {
                        int p2 = pos + __popc(m & ((1u << lane) - 1u));
                        if (p2 < 32) s32[p2] = kk;
                    }
                    pos += __popc(m);
                }
#pragma unroll
                for (int d = 16; d; d >>= 1)
                    mna = min(mna, __shfl_xor_sync(full, mna, d));
                __syncwarp();
                if (cc <= 32) {
                    unsigned vv = (lane < cc) ? s32[lane] : 0xffffffffu;
#pragma unroll
                    for (int k2 = 2; k2 <= 32; k2 <<= 1)
#pragma unroll
                        for (int j = k2 >> 1; j; j >>= 1) {
                            unsigned o = __shfl_xor_sync(full, vv, j);
                            bool keepMin = ((lane & j) == 0) == ((lane & k2) == 0);
                            vv = keepMin ? min(vv, o) : max(vv, o);
                        }
                    k0 = __shfl_sync(full, vv, lrr);
                    unsigned k1n = __shfl_sync(full, vv, (lrr + 1) & 31);
                    k1 = (lrr + 1 < cc) ? k1n : mna;
                } else {
                    // sh reached 0 with cc>32: all matching keys identical
                    k0 = s32[0];
                    k1 = (lrr + 1 < cc) ? k0 : mna;
                }
            }
            v0 = key2f(k0);
            if (need1) v1 = key2f(k1);
        } else {
            const unsigned* row = sm + ts * RS;
            v0 = key2f(generic_select_row(row, lane, R0[v]));
            if (need1) v1 = key2f(generic_select_row(row, lane, R0[v] + 1));
        }
        if (lane == 0) {
            float* qo = qout + ts * 8;
            if (v == 0) { qo[0] = v0; qo[1] = v1; }
            else if (v == 1) { qo[2] = v0; }
            else { qo[3] = v0; qo[4] = v1; }
        }
    }
    __syncthreads();

    // ---- phase 4: finalize (warp 0, lanes 0..3 -> one series each) ----
    if (w == 0 && lane < SPB) {
        int ts = lane;
        float ts1 = 0.f, ts2 = 0.f, ts3 = 0.f, ts4 = 0.f;
        float tmn = INFINITY, tmx = -INFINITY;
#pragma unroll
        for (int w2 = 0; w2 < 8; w2++) {
            const unsigned* r = sm + REC_OFF + (w2 * 4 + ts) * 12;
            ts1 += __uint_as_float(r[0]); ts2 += __uint_as_float(r[1]);
            ts3 += __uint_as_float(r[2]); ts4 += __uint_as_float(r[3]);
            tmn = fminf(tmn, __uint_as_float(r[4]));
            tmx = fmaxf(tmx, __uint_as_float(r[5]));
        }
        const float* qo = qout + ts * 8;
        const float n = 2048.f;
        float mean = ts1 / n;
        float m2 = ts2 / n, m3 = ts3 / n, m4 = ts4 / n;
        float varp = m2 - mean * mean;
        float var1 = varp * (n / (n - 1.f));
        float sd = sqrtf(var1);
        float mu2 = mean * mean;
        float m4c = m4 - 4.f * mean * m3 + 6.f * mu2 * m2 - 3.f * mu2 * mu2;
        float kurt = m4c / (var1 * var1) - 3.f;
        float q25 = 0.25f * qo[0] + 0.75f * qo[1];   // pos 511.75
        float med = qo[2];                            // pos 1023
        float q75 = 0.75f * qo[3] + 0.25f * qo[4];   // pos 1535.25

        int jg = part * SPB + ts;                     // 0..23
        int base = (jg < 12) ? 0 : 8;
        int col  = (jg < 12) ? jg : (jg - 12);
        float* o = g_stat2 + ((size_t)bc * 16 + base) * 12 + col;
        o[0 * 12] = tmx;
        o[1 * 12] = q25;
        o[2 * 12] = med;
        o[3 * 12] = q75;
        o[4 * 12] = mean;
        o[5 * 12] = sd;
        o[6 * 12] = tmx - tmn;
        o[7 * 12] = kurt;
    }

    // ---- weff tail folded in: blocks 0..119, threads 0..127 ----
    if (blk < 120 && tid < 128) {
        int idx = blk * 128 + tid;                    // 0 .. 15359
        int j   = idx % 12;
        int sx  = (idx / 12) & 15;
        int cx  = (idx / 192) & 15;
        int cls = idx / 3072;
        float a = 0.f;
#pragma unroll 8
        for (int e = 0; e < 64; e++)
            a += __ldg(&Wl[cls * 1024 + e * 16 + sx]) *
                 __ldg(&W2[(e * 16 + cx) * 12 + j]);
        g_weff[idx] = a;
    }
}

// ---------------------------------------------------------------------------
// Kernel B: logits[b,cls] = dot(stat2[b], weff[cls]) + sum b2*Wl + bl
// ---------------------------------------------------------------------------
__global__ __launch_bounds__(128)
void logits_kernel(const float* __restrict__ Wl, const float* __restrict__ b2,
                   const float* __restrict__ bl, float* __restrict__ out) {
    __shared__ float part[4];
    const unsigned full = 0xffffffffu;
    int blk = blockIdx.x;
    int b = blk / 5, cls = blk - b * 5;
    int tid = threadIdx.x;
    const float* st = g_stat2 + (size_t)b * 3072;
    const float* wf = g_weff + (size_t)cls * 3072;
    float a = 0.f;
    for (int i = tid; i < 3072; i += 128) a += st[i] * wf[i];
    for (int k = tid; k < 1024; k += 128)
        a += __ldg(&b2[k >> 4]) * __ldg(&Wl[cls * 1024 + k]);
#pragma unroll
    for (int d = 16; d; d >>= 1) a += __shfl_xor_sync(full, a, d);
    if ((tid & 31) == 0) part[tid >> 5] = a;
    __syncthreads();
    if (tid == 0)
        out[b * 5 + cls] = part[0] + part[1] + part[2] + part[3] + bl[cls];
}

// ---------------------------------------------------------------------------
extern "C" void kernel_launch(void* const* d_in, const int* in_sizes, int n_in,
                              void* d_out, int out_size) {
    const float* features = (const float*)d_in[0];
    // d_in[1]=W1, d_in[2]=b1 : dead in the reference (result discarded)
    const float* W2 = (const float*)d_in[3];
    const float* b2 = (const float*)d_in[4];
    const float* Wl = (const float*)d_in[5];
    const float* bl = (const float*)d_in[6];
    float* out = (float*)d_out;

    cudaFuncSetAttribute(stats_kernel,
                         cudaFuncAttributeMaxDynamicSharedMemorySize,
                         SMEM_BYTES);

    stats_kernel<<<BB * CC * NPARTS, NT, SMEM_BYTES>>>(features, W2, Wl);
    logits_kernel<<<BB * 5, 128>>>(Wl, b2, bl, out);
}

// round 13
// speedup vs baseline: 1.4321x; 1.2382x over previous
#include <cuda_runtime.h>
#include <math.h>
#include <stdint.h>

// Problem constants
#define BB 64
#define CC 16
#define FF 2048
#define JT 25            // stored joints per feature row
#define SPB 4            // series per block
#define NPARTS 6         // 24 joints / 4
#define NT 256           // 8 warps
#define RS 2056          // padded row stride (words)
#define WCAP 288         // per (series,window) key capacity (~6.2 sigma mid)

#define DATA_WORDS (SPB * RS)                 // 8224
#define CAND_OFF   DATA_WORDS                 // 8224  (12 arrays: (ts*3+v)*WCAP)
#define HIST_OFF   (CAND_OFF + 12 * WCAP)     // 11680
#define REC_OFF    (HIST_OFF + 8 * 256)       // 13728 (32 records x 12 words)
#define CNT_OFF    (REC_OFF + 32 * 12)        // 14112
#define OFF_OFF    (CNT_OFF + 256)            // 14368
#define QOUT_OFF   (OFF_OFF + 256)            // 14624
#define SMEM_WORDS (QOUT_OFF + 32)            // 14656
#define SMEM_BYTES (SMEM_WORDS * 4)           // 58624 -> 3 blocks/SM

__device__ float g_stat2[BB * CC * 16 * 12];   // (b, c, s, j)
__device__ float g_weff[5 * 16 * 16 * 12];     // (cls, c, s, j)

__device__ __forceinline__ unsigned f2key(float x) {
    unsigned b = __float_as_uint(x);
    return b ^ ((unsigned)(((int)b) >> 31) | 0x80000000u);
}
__device__ __forceinline__ float key2f(unsigned k) {
    unsigned u = (k & 0x80000000u) ? (k & 0x7fffffffu) : ~k;
    return __uint_as_float(u);
}

// ---------------------------------------------------------------------------
// 256-bin histogram rank search (warp-uniform r). Returns bin; updates r to
// rank-within-bin; outputs bin count.
// ---------------------------------------------------------------------------
__device__ __forceinline__ int warp_find_bin256(const unsigned* hist, int lane,
                                                int& r, int& bincount) {
    const unsigned full = 0xffffffffu;
    unsigned c[8]; unsigned run = 0;
#pragma unroll
    for (int t = 0; t < 8; t++) { c[t] = hist[lane * 8 + t]; run += c[t]; }
    unsigned inc = run;
#pragma unroll
    for (int d = 1; d < 32; d <<= 1) {
        unsigned v = __shfl_up_sync(full, inc, d);
        if (lane >= d) inc += v;
    }
    unsigned acc = inc - run;
    int bin = -1, newr = 0; unsigned bc = 0;
#pragma unroll
    for (int t = 0; t < 8; t++) {
        if (bin < 0 && (int)acc <= r && r < (int)(acc + c[t])) {
            bin = lane * 8 + t; newr = r - (int)acc; bc = c[t];
        }
        acc += c[t];
    }
    unsigned m = __ballot_sync(full, bin >= 0);
    int srcl = __ffs(m) - 1;
    bin  = __shfl_sync(full, bin, srcl);
    newr = __shfl_sync(full, newr, srcl);
    bc   = __shfl_sync(full, bc, srcl);
    r = newr; bincount = (int)bc;
    return bin;
}

// ---------------------------------------------------------------------------
// Correctness fallback: exact rank-r key via bisection over the intact row.
// ---------------------------------------------------------------------------
__device__ unsigned generic_select_row(const unsigned* row, int lane, int r) {
    const unsigned full = 0xffffffffu;
    unsigned Klo = 0u, Khi = 0xffffffffu;
#pragma unroll 1
    while (Klo < Khi) {
        unsigned mid = Klo + ((Khi - Klo) >> 1);
        int cle = 0;
        for (int i = 0; i < 64; i++)
            cle += (f2key(__uint_as_float(row[i * 32 + lane])) <= mid);
#pragma unroll
        for (int d = 16; d; d >>= 1) cle += __shfl_xor_sync(full, cle, d);
        if (r < cle) Khi = mid; else Klo = mid + 1u;
    }
    return Klo;
}

// ---------------------------------------------------------------------------
// Kernel A: one block per (b,c,part). Mask-based single-scan pipeline:
// phase 1 = load+moments+masks; phase 2 = packed scan + direct scatter of
// pre-filtered KEYS per (series,window); phase 3 = selection (no pass A).
// ---------------------------------------------------------------------------
__global__ __launch_bounds__(NT)
void stats_kernel(const float* __restrict__ features,
                  const float* __restrict__ W2, const float* __restrict__ Wl) {
    extern __shared__ unsigned sm[];
    const unsigned full = 0xffffffffu;

    const int blk  = blockIdx.x;
    const int bc   = blk / NPARTS;
    const int part = blk - bc * NPARTS;       // 0..5 -> joints part*4 .. +3
    const int tid  = threadIdx.x;
    const int w    = tid >> 5;
    const int lane = tid & 31;
    const int jj   = tid & 3;                 // joint within part
    const int f0   = tid >> 2;                // f base (0..63)

    const float* src = features + (size_t)bc * (FF * JT) + part * 4;
    float* smf = reinterpret_cast<float*>(sm);

    // window pivots (data ~N(0,1); smem bisection fallback covers the rest)
    const float P0 = -0.80f, P1 = -0.55f, P2 = -0.125f,
                P3 =  0.125f, P4 =  0.55f, P5 =  0.80f;

    // ---- phase 1: load + transpose + moments + counts + window masks ----
    unsigned m0 = 0u, m1 = 0u, m2 = 0u;
    {
        float s1 = 0.f, s2 = 0.f, s3 = 0.f, s4 = 0.f;
        float mn = INFINITY, mx = -INFINITY;
        int c0 = 0, c2 = 0, c4 = 0;           // counts below P0, P2, P4
#pragma unroll 8
        for (int k = 0; k < 32; k++) {
            int f = f0 + 64 * k;
            float x = __ldg(src + (size_t)f * JT + jj);
            smf[jj * RS + f] = x;
            s1 += x;
            float x2 = x * x;
            s2 += x2; s3 += x2 * x; s4 += x2 * x2;
            mn = fminf(mn, x); mx = fmaxf(mx, x);
            bool b0 = x < P0, b1 = x < P1, b2 = x < P2,
                 b3 = x < P3, b4 = x < P4, b5 = x < P5;
            c0 += b0; c2 += b2; c4 += b4;
            if (b1 && !b0) m0 |= 1u << k;
            if (b3 && !b2) m1 |= 1u << k;
            if (b5 && !b4) m2 |= 1u << k;
        }
        int n0 = __popc(m0), n1 = __popc(m1), n2 = __popc(m2);
        // per-thread packed window counts (10-bit fields)
        sm[CNT_OFF + tid] = (unsigned)n0 | ((unsigned)n1 << 10)
                          | ((unsigned)n2 << 20);
        // reduce over the 8 lanes sharing jj (xor 4,8,16 preserves lane&3)
#pragma unroll
        for (int d = 4; d <= 16; d <<= 1) {
            s1 += __shfl_xor_sync(full, s1, d);
            s2 += __shfl_xor_sync(full, s2, d);
            s3 += __shfl_xor_sync(full, s3, d);
            s4 += __shfl_xor_sync(full, s4, d);
            mn = fminf(mn, __shfl_xor_sync(full, mn, d));
            mx = fmaxf(mx, __shfl_xor_sync(full, mx, d));
            c0 += __shfl_xor_sync(full, c0, d);
            c2 += __shfl_xor_sync(full, c2, d);
            c4 += __shfl_xor_sync(full, c4, d);
            n0 += __shfl_xor_sync(full, n0, d);
            n1 += __shfl_xor_sync(full, n1, d);
            n2 += __shfl_xor_sync(full, n2, d);
        }
        if (lane < 4) {     // lane == jj for these lanes
            unsigned* r = sm + REC_OFF + (w * 4 + lane) * 12;
            r[0] = __float_as_uint(s1); r[1] = __float_as_uint(s2);
            r[2] = __float_as_uint(s3); r[3] = __float_as_uint(s4);
            r[4] = __float_as_uint(mn); r[5] = __float_as_uint(mx);
            r[6] = (unsigned)c0; r[7] = (unsigned)c2; r[8] = (unsigned)c4;
            r[9] = (unsigned)n0; r[10] = (unsigned)n1; r[11] = (unsigned)n2;
        }
    }
    __syncthreads();

    // ---- phase 2a: packed per-series exclusive scan (warps 0..3) ----
    if (w < 4) {
        unsigned ca = sm[CNT_OFF + 8 * lane + w];
        unsigned cb = sm[CNT_OFF + 8 * lane + 4 + w];
        unsigned ps = ca + cb;
        unsigned inc = ps;
#pragma unroll
        for (int d = 1; d < 32; d <<= 1) {
            unsigned v = __shfl_up_sync(full, inc, d);
            if (lane >= d) inc += v;
        }
        unsigned ex = inc - ps;
        sm[OFF_OFF + 8 * lane + w] = ex;
        sm[OFF_OFF + 8 * lane + 4 + w] = ex + ca;
    }
    __syncthreads();

    // ---- phase 2b: scatter pre-converted keys, split per window ----
    {
        unsigned offp = sm[OFF_OFF + tid];
        int o0 = offp & 1023, o1 = (offp >> 10) & 1023, o2 = (offp >> 20) & 1023;
        unsigned* cbase = sm + CAND_OFF + jj * (3 * WCAP);
        unsigned mall = m0 | m1 | m2;
        while (mall) {
            int k = __ffs(mall) - 1; mall &= mall - 1;
            float x = smf[jj * RS + f0 + 64 * k];
            unsigned key = f2key(x);
            if ((m0 >> k) & 1) { if (o0 < WCAP) cbase[o0] = key; o0++; }
            else if ((m1 >> k) & 1) { if (o1 < WCAP) cbase[WCAP + o1] = key; o1++; }
            else { if (o2 < WCAP) cbase[2 * WCAP + o2] = key; o2++; }
        }
    }
    __syncthreads();

    // ---- phase 3: 12 selection tasks over 8 warps ----
    const int R0[3] = {511, 1023, 1535};
    unsigned* hist = sm + HIST_OFF + w * 256;
    float* qout = reinterpret_cast<float*>(sm + QOUT_OFF);

#pragma unroll 1
    for (int pass = 0; pass < 2; pass++) {
        int t = (pass == 0) ? w : (w < 4 ? 8 + w : -1);
        if (t < 0) break;
        int ts = t / 3, v = t - ts * 3;
        int need1 = (v != 1);

        // exact counts from records (lanes 0..7 hold warp-records of ts)
        int cl = 0, w0 = 0, w1 = 0, w2 = 0;
        if (lane < 8) {
            const unsigned* r = sm + REC_OFF + (lane * 4 + ts) * 12;
            cl = (int)r[6 + v];
            w0 = (int)r[9]; w1 = (int)r[10]; w2 = (int)r[11];
        }
#pragma unroll
        for (int d = 1; d <= 4; d <<= 1) {
            cl += __shfl_xor_sync(full, cl, d);
            w0 += __shfl_xor_sync(full, w0, d);
            w1 += __shfl_xor_sync(full, w1, d);
            w2 += __shfl_xor_sync(full, w2, d);
        }
        cl = __shfl_sync(full, cl, 0);
        w0 = __shfl_sync(full, w0, 0);
        w1 = __shfl_sync(full, w1, 0);
        w2 = __shfl_sync(full, w2, 0);
        int wc = (v == 0) ? w0 : (v == 1) ? w1 : w2;
        int wmax = max(w0, max(w1, w2));
        int lr = R0[v] - cl;

        // fast path valid: offsets exact (no 10-bit carry), capacity, bracket
        bool ok = (wmax <= 1023) && (wc <= WCAP) && (lr >= 0) &&
                  ((lr + need1) < wc);
        float v0, v1 = 0.f;
        if (ok) {
            const unsigned* cnd = sm + CAND_OFF + (ts * 3 + v) * WCAP;
            // minmax over the pre-filtered keys
            unsigned kmn = 0xffffffffu, kmx = 0u;
            for (int idx = lane; idx < wc; idx += 32) {
                unsigned k = cnd[idx];
                kmn = min(kmn, k); kmx = max(kmx, k);
            }
#pragma unroll
            for (int d = 16; d; d >>= 1) {
                kmn = min(kmn, __shfl_xor_sync(full, kmn, d));
                kmx = max(kmx, __shfl_xor_sync(full, kmx, d));
            }
            __syncwarp();

            unsigned k0, k1;
            if (kmn == kmx) {
                k0 = kmn; k1 = kmn;
            } else {
                // adaptive 8-bit radix rounds directly on cnd
                unsigned prefix = 0u, pmask = 0u;
                unsigned diff = kmn ^ kmx;
                int hib = 31 - __clz(diff);
                int sh = hib > 7 ? hib - 7 : 0;
                int cc = wc, lrr = lr;
#pragma unroll 1
                for (int round = 0; round < 5; round++) {
#pragma unroll
                    for (int u = 0; u < 8; u++) hist[lane + u * 32] = 0u;
                    __syncwarp();
                    for (int idx = lane; idx < wc; idx += 32) {
                        unsigned kk = cnd[idx];
                        if ((kk & pmask) == prefix)
                            atomicAdd(&hist[(kk >> sh) & 0xFFu], 1u);
                    }
                    __syncwarp();
                    int bcnt;
                    int b = warp_find_bin256(hist, lane, lrr, bcnt);
                    prefix |= (unsigned)b << sh;
                    pmask  |= 0xFFu << sh;
                    cc = bcnt;
                    __syncwarp();
                    if (cc <= 32 || sh == 0) break;
                    sh = (sh >= 8) ? sh - 8 : 0;
                }
                // final gather of matching keys (<=32, or all-identical)
                unsigned* s32 = hist;   // hist dead now
                unsigned mna = 0xffffffffu;
                int pos = 0;
                for (int base = 0; base < wc; base += 32) {
                    int idx = base + lane;
                    bool match = false; unsigned kk = 0u;
                    if (idx < wc) {
                        kk = cnd[idx];
                        unsigned masked = kk & pmask;
                        if (masked == prefix) match = true;
                        else if (masked > prefix) mna = min(mna, kk);
                    }
                    unsigned m = __ballot_sync(full, match);
                    if (match) {
                        int p2 = pos + __popc(m & ((1u << lane) - 1u));
                        if (p2 < 32) s32[p2] = kk;
                    }
                    pos += __popc(m);
                }
#pragma unroll
                for (int d = 16; d; d >>= 1)
                    mna = min(mna, __shfl_xor_sync(full, mna, d));
                __syncwarp();
                if (cc <= 32) {
                    unsigned vv = (lane < cc) ? s32[lane] : 0xffffffffu;
#pragma unroll
                    for (int k2 = 2; k2 <= 32; k2 <<= 1)
#pragma unroll
                        for (int j = k2 >> 1; j; j >>= 1) {
                            unsigned o = __shfl_xor_sync(full, vv, j);
                            bool keepMin = ((lane & j) == 0) == ((lane & k2) == 0);
                            vv = keepMin ? min(vv, o) : max(vv, o);
                        }
                    k0 = __shfl_sync(full, vv, lrr);
                    unsigned k1n = __shfl_sync(full, vv, (lrr + 1) & 31);
                    k1 = (lrr + 1 < cc) ? k1n : mna;
                } else {
                    // sh reached 0 with cc>32: all matching keys identical
                    k0 = s32[0];
                    k1 = (lrr + 1 < cc) ? k0 : mna;
                }
            }
            v0 = key2f(k0);
            if (need1) v1 = key2f(k1);
        } else {
            const unsigned* row = sm + ts * RS;
            v0 = key2f(generic_select_row(row, lane, R0[v]));
            if (need1) v1 = key2f(generic_select_row(row, lane, R0[v] + 1));
        }
        if (lane == 0) {
            float* qo = qout + ts * 8;
            if (v == 0) { qo[0] = v0; qo[1] = v1; }
            else if (v == 1) { qo[2] = v0; }
            else { qo[3] = v0; qo[4] = v1; }
        }
    }
    __syncthreads();

    // ---- phase 4: finalize (warp 0, lanes 0..3 -> one series each) ----
    if (w == 0 && lane < SPB) {
        int ts = lane;
        float ts1 = 0.f, ts2 = 0.f, ts3 = 0.f, ts4 = 0.f;
        float tmn = INFINITY, tmx = -INFINITY;
#pragma unroll
        for (int w2 = 0; w2 < 8; w2++) {
            const unsigned* r = sm + REC_OFF + (w2 * 4 + ts) * 12;
            ts1 += __uint_as_float(r[0]); ts2 += __uint_as_float(r[1]);
            ts3 += __uint_as_float(r[2]); ts4 += __uint_as_float(r[3]);
            tmn = fminf(tmn, __uint_as_float(r[4]));
            tmx = fmaxf(tmx, __uint_as_float(r[5]));
        }
        const float* qo = qout + ts * 8;
        const float n = 2048.f;
        float mean = ts1 / n;
        float m2 = ts2 / n, m3 = ts3 / n, m4 = ts4 / n;
        float varp = m2 - mean * mean;
        float var1 = varp * (n / (n - 1.f));
        float sd = sqrtf(var1);
        float mu2 = mean * mean;
        float m4c = m4 - 4.f * mean * m3 + 6.f * mu2 * m2 - 3.f * mu2 * mu2;
        float kurt = m4c / (var1 * var1) - 3.f;
        float q25 = 0.25f * qo[0] + 0.75f * qo[1];   // pos 511.75
        float med = qo[2];                            // pos 1023
        float q75 = 0.75f * qo[3] + 0.25f * qo[4];   // pos 1535.25

        int jg = part * SPB + ts;                     // 0..23
        int base = (jg < 12) ? 0 : 8;
        int col  = (jg < 12) ? jg : (jg - 12);
        float* o = g_stat2 + ((size_t)bc * 16 + base) * 12 + col;
        o[0 * 12] = tmx;
        o[1 * 12] = q25;
        o[2 * 12] = med;
        o[3 * 12] = q75;
        o[4 * 12] = mean;
        o[5 * 12] = sd;
        o[6 * 12] = tmx - tmn;
        o[7 * 12] = kurt;
    }

    // ---- weff tail folded in: blocks 0..119, threads 0..127 ----
    if (blk < 120 && tid < 128) {
        int idx = blk * 128 + tid;                    // 0 .. 15359
        int j   = idx % 12;
        int sx  = (idx / 12) & 15;
        int cx  = (idx / 192) & 15;
        int cls = idx / 3072;
        float a = 0.f;
#pragma unroll 8
        for (int e = 0; e < 64; e++)
            a += __ldg(&Wl[cls * 1024 + e * 16 + sx]) *
                 __ldg(&W2[(e * 16 + cx) * 12 + j]);
        g_weff[idx] = a;
    }
}

// ---------------------------------------------------------------------------
// Kernel B: logits[b,cls] = dot(stat2[b], weff[cls]) + sum b2*Wl + bl
// ---------------------------------------------------------------------------
__global__ __launch_bounds__(128)
void logits_kernel(const float* __restrict__ Wl, const float* __restrict__ b2,
                   const float* __restrict__ bl, float* __restrict__ out) {
    __shared__ float part[4];
    const unsigned full = 0xffffffffu;
    int blk = blockIdx.x;
    int b = blk / 5, cls = blk - b * 5;
    int tid = threadIdx.x;
    const float* st = g_stat2 + (size_t)b * 3072;
    const float* wf = g_weff + (size_t)cls * 3072;
    float a = 0.f;
    for (int i = tid; i < 3072; i += 128) a += st[i] * wf[i];
    for (int k = tid; k < 1024; k += 128)
        a += __ldg(&b2[k >> 4]) * __ldg(&Wl[cls * 1024 + k]);
#pragma unroll
    for (int d = 16; d; d >>= 1) a += __shfl_xor_sync(full, a, d);
    if ((tid & 31) == 0) part[tid >> 5] = a;
    __syncthreads();
    if (tid == 0)
        out[b * 5 + cls] = part[0] + part[1] + part[2] + part[3] + bl[cls];
}

// ---------------------------------------------------------------------------
extern "C" void kernel_launch(void* const* d_in, const int* in_sizes, int n_in,
                              void* d_out, int out_size) {
    const float* features = (const float*)d_in[0];
    // d_in[1]=W1, d_in[2]=b1 : dead in the reference (result discarded)
    const float* W2 = (const float*)d_in[3];
    const float* b2 = (const float*)d_in[4];
    const float* Wl = (const float*)d_in[5];
    const float* bl = (const float*)d_in[6];
    float* out = (float*)d_out;

    cudaFuncSetAttribute(stats_kernel,
                         cudaFuncAttributeMaxDynamicSharedMemorySize,
                         SMEM_BYTES);

    stats_kernel<<<BB * CC * NPARTS, NT, SMEM_BYTES>>>(features, W2, Wl);
    logits_kernel<<<BB * 5, 128>>>(Wl, b2, bl, out);
}